// round 15
// baseline (speedup 1.0000x reference)
#include <cuda_runtime.h>
#include <math.h>

#define CC 48
#define TT 400
#define FF 129
#define BB 2
#define TFT 51600        // T*F
#define CTF 2476800      // C*T*F
#define BCTF 4953600     // B*C*T*F
#define OC 96
#define OUT_SZ 9907200   // B*OC*T*F

typedef unsigned long long u64;

// ---- tf32 helpers (validated R12-R14: correct layouts, rel_err 2.9e-4) ----
__device__ __forceinline__ float tf32r(float x) {
    unsigned y; asm("cvt.rna.tf32.f32 %0, %1;" : "=r"(y) : "f"(x));
    return __uint_as_float(y);
}
__device__ __forceinline__ void mma_tf32(
    float &c0, float &c1, float &c2, float &c3,
    unsigned a0, unsigned a1, unsigned a2, unsigned a3,
    unsigned b0, unsigned b1)
{
    asm("mma.sync.aligned.m16n8k8.row.col.f32.tf32.tf32.f32 "
        "{%0,%1,%2,%3}, {%4,%5,%6,%7}, {%8,%9}, {%0,%1,%2,%3};"
        : "+f"(c0), "+f"(c1), "+f"(c2), "+f"(c3)
        : "r"(a0), "r"(a1), "r"(a2), "r"(a3), "r"(b0), "r"(b1));
}

// Scratch
__device__ __align__(16) float g_Q[BCTF];
__device__ __align__(16) float g_K[BCTF];
__device__ __align__(16) float g_Kref[BCTF];
__device__ __align__(16) float g_ref[BCTF];

// ===========================================================================
// Kernel 1: pw (exact R10 version)
// ===========================================================================
#define PW_P 128
#define PW_NB 404
#define SMEM_PW ((2*CC*CC + 2*CC + 2*CC*PW_P)*4)   // 67,968 B

__global__ __launch_bounds__(384) void pw_kernel(
    const float* __restrict__ x_mic, const float* __restrict__ x_ref,
    const float* __restrict__ dw1w, const float* __restrict__ dw1b,
    const float* __restrict__ pw1w, const float* __restrict__ pw1b,
    const float* __restrict__ dw2w, const float* __restrict__ dw2b,
    const float* __restrict__ pw2w, const float* __restrict__ pw2b,
    const float* __restrict__ dw3w, const float* __restrict__ dw3b,
    const float* __restrict__ pw3w, const float* __restrict__ pw3b)
{
    extern __shared__ float smp[];
    float* W1T = smp;
    float* W2T = W1T + CC*CC;
    float* bb1 = W2T + CC*CC;
    float* bb2 = bb1 + CC;
    float* xs  = bb2 + CC;
    float* qs  = xs + CC*PW_P;

    const int tid = threadIdx.x;
    const int b = blockIdx.y, job = blockIdx.z;
    const int p0 = blockIdx.x * PW_P;
    const float* x   = job ? x_ref : x_mic;
    const float* w1  = job ? pw3w : pw1w;
    const float* d1w = job ? dw3w : dw1w;
    const float* p1b = job ? pw3b : pw1b;
    const float* d1b = job ? dw3b : dw1b;

    for (int i = tid; i < CC*CC; i += 384) {
        int o = i / CC, c = i % CC;
        W1T[c*CC+o] = w1[i] * d1w[c];
        if (!job) W2T[c*CC+o] = pw2w[i] * dw2w[c];
    }
    if (tid < CC) {
        float s1 = p1b[tid];
        for (int c = 0; c < CC; c++) s1 += w1[tid*CC+c] * d1b[c];
        bb1[tid] = s1;
        if (!job) {
            float s2 = pw2b[tid];
            for (int c = 0; c < CC; c++) s2 += pw2w[tid*CC+c] * dw2b[c];
            bb2[tid] = s2;
        }
    }
    for (int i = tid; i < CC*PW_P; i += 384) {
        int c = i / PW_P, p = i % PW_P;
        int gp = p0 + p;
        xs[i] = (gp < TFT) ? x[(size_t)b*CTF + (size_t)c*TFT + gp] : 0.f;
    }
    __syncthreads();

    const int ot = tid >> 5, pt = tid & 31;
    const int o0 = ot*4, pp = pt*4;
    const int gp0 = p0 + pp;
    float* out1 = job ? g_Kref : g_Q;

    {
        float4 a0={0,0,0,0},a1={0,0,0,0},a2={0,0,0,0},a3={0,0,0,0};
        #pragma unroll 4
        for (int c = 0; c < CC; c++) {
            float4 w  = *(const float4*)&W1T[c*CC+o0];
            float4 xv = *(const float4*)&xs[c*PW_P+pp];
            a0.x+=w.x*xv.x; a0.y+=w.x*xv.y; a0.z+=w.x*xv.z; a0.w+=w.x*xv.w;
            a1.x+=w.y*xv.x; a1.y+=w.y*xv.y; a1.z+=w.y*xv.z; a1.w+=w.y*xv.w;
            a2.x+=w.z*xv.x; a2.y+=w.z*xv.y; a2.z+=w.z*xv.z; a2.w+=w.z*xv.w;
            a3.x+=w.w*xv.x; a3.y+=w.w*xv.y; a3.z+=w.w*xv.z; a3.w+=w.w*xv.w;
        }
        float4 bv = *(const float4*)&bb1[o0];
        a0.x+=bv.x; a0.y+=bv.x; a0.z+=bv.x; a0.w+=bv.x;
        a1.x+=bv.y; a1.y+=bv.y; a1.z+=bv.y; a1.w+=bv.y;
        a2.x+=bv.z; a2.y+=bv.z; a2.z+=bv.z; a2.w+=bv.z;
        a3.x+=bv.w; a3.y+=bv.w; a3.z+=bv.w; a3.w+=bv.w;
        if (!job) {
            *(float4*)&qs[(o0+0)*PW_P+pp] = a0;
            *(float4*)&qs[(o0+1)*PW_P+pp] = a1;
            *(float4*)&qs[(o0+2)*PW_P+pp] = a2;
            *(float4*)&qs[(o0+3)*PW_P+pp] = a3;
        }
        if (gp0 < TFT) {
            size_t base = (size_t)b*CTF + gp0;
            *(float4*)&out1[base + (size_t)(o0+0)*TFT] = a0;
            *(float4*)&out1[base + (size_t)(o0+1)*TFT] = a1;
            *(float4*)&out1[base + (size_t)(o0+2)*TFT] = a2;
            *(float4*)&out1[base + (size_t)(o0+3)*TFT] = a3;
        }
    }
    if (job) return;
    __syncthreads();

    {
        float4 a0={0,0,0,0},a1={0,0,0,0},a2={0,0,0,0},a3={0,0,0,0};
        #pragma unroll 4
        for (int c = 0; c < CC; c++) {
            float4 w  = *(const float4*)&W2T[c*CC+o0];
            float4 xv = *(const float4*)&qs[c*PW_P+pp];
            a0.x+=w.x*xv.x; a0.y+=w.x*xv.y; a0.z+=w.x*xv.z; a0.w+=w.x*xv.w;
            a1.x+=w.y*xv.x; a1.y+=w.y*xv.y; a1.z+=w.y*xv.z; a1.w+=w.y*xv.w;
            a2.x+=w.z*xv.x; a2.y+=w.z*xv.y; a2.z+=w.z*xv.z; a2.w+=w.z*xv.w;
            a3.x+=w.w*xv.x; a3.y+=w.w*xv.y; a3.z+=w.w*xv.z; a3.w+=w.w*xv.w;
        }
        float4 bv = *(const float4*)&bb2[o0];
        a0.x+=bv.x; a0.y+=bv.x; a0.z+=bv.x; a0.w+=bv.x;
        a1.x+=bv.y; a1.y+=bv.y; a1.z+=bv.y; a1.w+=bv.y;
        a2.x+=bv.z; a2.y+=bv.z; a2.z+=bv.z; a2.w+=bv.z;
        a3.x+=bv.w; a3.y+=bv.w; a3.z+=bv.w; a3.w+=bv.w;
        if (gp0 < TFT) {
            size_t base = (size_t)b*CTF + gp0;
            *(float4*)&g_K[base + (size_t)(o0+0)*TFT] = a0;
            *(float4*)&g_K[base + (size_t)(o0+1)*TFT] = a1;
            *(float4*)&g_K[base + (size_t)(o0+2)*TFT] = a2;
            *(float4*)&g_K[base + (size_t)(o0+3)*TFT] = a3;
        }
    }
}

// ===========================================================================
// Kernel 2: mic attention via tf32 mma, 512 threads (R12 was occ-starved at
// 8 warps/SM; same fix as R14 fusion). Scores: 18 units (9 m-tiles x 2
// n-halves) over 16 warps, A-frags cached per unit. AV: 51 jobs / 16 warps.
// ===========================================================================
#define QSTR 52
#define SSTR 137
#define XSTR 140
#define SM_Q 0
#define SM_K (SM_Q + 144*QSTR)
#define SM_X (SM_K + 136*QSTR)
#define SM_S (SM_X + 48*XSTR)
#define SM_IV (SM_S + 136*SSTR)
#define SMEM_MMA ((SM_IV + 132)*4)   // 160,176 B

__global__ __launch_bounds__(512) void mic_attn_kernel(
    const float* __restrict__ x_mic, float* __restrict__ mic_out)
{
    extern __shared__ float sm[];
    float* Qs = sm + SM_Q;
    float* Ks = sm + SM_K;
    float* Xs = sm + SM_X;
    float* Ss = sm + SM_S;
    float* SIv = sm + SM_IV;

    const int tid = threadIdx.x;
    const int t = blockIdx.x, b = blockIdx.y;
    const size_t rbase = (size_t)b*CTF + (size_t)t*FF;

    for (int i = tid; i < CC*144; i += 512) {
        int c = i / 144, f = i % 144;
        Qs[f*QSTR + c] = (f < FF) ? tf32r(g_Q[rbase + (size_t)c*TFT + f]) : 0.f;
    }
    for (int i = tid; i < CC*136; i += 512) {
        int c = i / 136, g = i % 136;
        Ks[g*QSTR + c] = (g < FF) ? tf32r(g_K[rbase + (size_t)c*TFT + g]) : 0.f;
    }
    for (int i = tid; i < CC*XSTR; i += 512) {
        int c = i / XSTR, g = i % XSTR;
        Xs[c*XSTR + g] = (g < FF) ? tf32r(x_mic[rbase + (size_t)c*TFT + g]) : 0.f;
    }
    __syncthreads();

    const int w = tid >> 5, lane = tid & 31;     // 16 warps
    const int tg = lane >> 2, t4 = lane & 3;

    // ---- scores: 18 units = (m-tile, n-half); A-frags cached per unit ----
    for (int unit = w; unit < 18; unit += 16) {
        const int mt = unit >> 1, h = unit & 1;
        const int m0 = mt * 16;
        const int ntBeg = h ? 9 : 0, ntEnd = h ? 17 : 9;
        unsigned a[6][4];
        #pragma unroll
        for (int kk = 0; kk < 6; kk++) {
            const float* q = &Qs[(m0 + tg)*QSTR + kk*8 + t4];
            a[kk][0] = __float_as_uint(q[0]);
            a[kk][1] = __float_as_uint(q[8*QSTR]);
            a[kk][2] = __float_as_uint(q[4]);
            a[kk][3] = __float_as_uint(q[8*QSTR + 4]);
        }
        for (int nt = ntBeg; nt < ntEnd; nt++) {
            const int n0 = nt * 8;
            float c0=0.f, c1=0.f, c2=0.f, c3=0.f;
            #pragma unroll
            for (int kk = 0; kk < 6; kk++) {
                const float* kp = &Ks[(n0 + tg)*QSTR + kk*8 + t4];
                unsigned b0 = __float_as_uint(kp[0]);
                unsigned b1 = __float_as_uint(kp[4]);
                mma_tf32(c0, c1, c2, c3,
                         a[kk][0], a[kk][1], a[kk][2], a[kk][3], b0, b1);
            }
            int r0 = m0 + tg, r1 = r0 + 8;
            int cc = n0 + 2*t4;
            if (r0 < FF) { Ss[r0*SSTR + cc] = c0; Ss[r0*SSTR + cc + 1] = c1; }
            if (r1 < FF) { Ss[r1*SSTR + cc] = c2; Ss[r1*SSTR + cc + 1] = c3; }
        }
    }
    __syncthreads();

    // ---- softmax per f-row (129 of 512 threads) ----
    if (tid < FF) {
        float* row = &Ss[tid*SSTR];
        const float rs = 0.14433756729740643f;
        float s0=0.f, s1=0.f, s2=0.f, s3=0.f;
        #pragma unroll 1
        for (int g = 0; g < 128; g += 4) {
            float e0 = tf32r(__expf(row[g+0]*rs));
            float e1 = tf32r(__expf(row[g+1]*rs));
            float e2 = tf32r(__expf(row[g+2]*rs));
            float e3 = tf32r(__expf(row[g+3]*rs));
            row[g+0]=e0; row[g+1]=e1; row[g+2]=e2; row[g+3]=e3;
            s0+=e0; s1+=e1; s2+=e2; s3+=e3;
        }
        float e = tf32r(__expf(row[128]*rs));
        row[128] = e;
        SIv[tid] = 1.f / (s0+s1+s2+s3+e);
    }
    __syncthreads();

    // ---- AV: 51 jobs over 16 warps ----
    for (int job = w; job < 51; job += 16) {
        const int m0 = (job / 17) * 16;
        const int n0 = (job % 17) * 8;
        float c0=0.f, c1=0.f, c2=0.f, c3=0.f;
        #pragma unroll 4
        for (int kk = 0; kk < 17; kk++) {
            const float* xp = &Xs[(m0 + tg)*XSTR + kk*8 + t4];
            unsigned a0 = __float_as_uint(xp[0]);
            unsigned a1 = __float_as_uint(xp[8*XSTR]);
            unsigned a2 = __float_as_uint(xp[4]);
            unsigned a3 = __float_as_uint(xp[8*XSTR + 4]);
            const float* pp = &Ss[(n0 + tg)*SSTR + kk*8 + t4];
            unsigned b0 = __float_as_uint(pp[0]);
            unsigned b1 = __float_as_uint(pp[4]);
            mma_tf32(c0, c1, c2, c3, a0, a1, a2, a3, b0, b1);
        }
        const int r0 = m0 + tg, r1 = r0 + 8;
        const int f0 = n0 + 2*t4;
        if (f0 < FF) {
            float iv = SIv[f0];
            mic_out[rbase + (size_t)r0*TFT + f0] = c0 * iv;
            mic_out[rbase + (size_t)r1*TFT + f0] = c2 * iv;
        }
        if (f0 + 1 < FF) {
            float iv = SIv[f0 + 1];
            mic_out[rbase + (size_t)r0*TFT + f0 + 1] = c1 * iv;
            mic_out[rbase + (size_t)r1*TFT + f0 + 1] = c3 * iv;
        }
    }
}

// ===========================================================================
// Kernel 3: ref attention (exact R10 version)
// ===========================================================================
#define RFP 132

__global__ __launch_bounds__(256) void ref_attn_kernel(const float* __restrict__ x_ref)
{
    __shared__ __align__(16) float krs[18*RFP];
    __shared__ __align__(16) float xrs[18*RFP];

    const int tid = threadIdx.x;
    const int t0 = blockIdx.x * 8;
    const int h = blockIdx.y, b = blockIdx.z;
    const size_t base = (size_t)b*CTF + (size_t)h*TFT;

    for (int i = tid; i < 18*RFP; i += 256) {
        int r = i / RFP, f = i % RFP;
        int tk = t0 - 10 + r;
        bool ok = (tk >= 0) && (f < FF);
        size_t gi = base + (size_t)tk*FF + f;
        krs[i] = ok ? g_Kref[gi] : 0.f;
        xrs[i] = ok ? x_ref[gi]  : 0.f;
    }
    __syncthreads();

    const int w = tid >> 5, lane = tid & 31;
    const int t = t0 + w;
    const size_t qbase = base + (size_t)t*FF;

    float qv[5], acc[5];
    bool val[5];
    #pragma unroll
    for (int k = 0; k < 5; k++) {
        int f = lane + 32*k;
        val[k] = f < FF;
        qv[k] = val[k] ? g_Q[qbase + f] : 0.f;
        acc[k] = 0.f;
    }

    for (int j = 0; j < 11; j++) {
        int tk = t - 10 + j;
        if (tk < 0) continue;
        int r = w + j;
        float e[5]; float s = 0.f;
        float xv[5];
        #pragma unroll
        for (int k = 0; k < 5; k++) {
            int f = lane + 32*k;
            float kv = val[k] ? krs[r*RFP+f] : 0.f;
            xv[k]    = val[k] ? xrs[r*RFP+f] : 0.f;
            e[k] = val[k] ? __expf(qv[k]*kv) : 0.f;
            s += e[k];
        }
        #pragma unroll
        for (int off = 16; off; off >>= 1) s += __shfl_xor_sync(0xffffffffu, s, off);
        float inv = 1.f/s;
        #pragma unroll
        for (int k = 0; k < 5; k++)
            acc[k] += xv[k] * (e[k]*inv);
    }
    #pragma unroll
    for (int k = 0; k < 5; k++) {
        int f = lane + 32*k;
        if (val[k]) g_ref[qbase + f] = acc[k];
    }
}

// ===========================================================================
// Kernel 4: fusion (exact R14 version, measured 67.4 µs)
// ===========================================================================
#define FP2 128
#define FNB 404
#define WRS 100
#define CTS 100
#define FSM_W 0
#define FSM_C (FSM_W + OC*WRS)
#define FSM_B (FSM_C + FP2*CTS)
#define FSM_A (FSM_B + OC)
#define SMEM_FUS ((FSM_A + OC)*4)    // 90,368 B

__global__ __launch_bounds__(512) void fusion_kernel(
    const float* __restrict__ fw, const float* __restrict__ fb,
    const float* __restrict__ gamma, const float* __restrict__ beta,
    const float* __restrict__ mean, const float* __restrict__ var,
    const float* __restrict__ prelu_a,
    const float* __restrict__ micp,
    float* __restrict__ outp)
{
    extern __shared__ float smf[];
    float* Wd    = smf + FSM_W;
    float* combT = smf + FSM_C;
    float* bias  = smf + FSM_B;
    float* alpha = smf + FSM_A;

    const int tid = threadIdx.x;
    const int b  = blockIdx.y;
    const int p0 = blockIdx.x * FP2;

    if (tid < OC) {
        float a = gamma[tid] * rsqrtf(var[tid] + 1e-5f);
        alpha[tid] = a;
        bias[tid] = (fb[tid] - mean[tid]) * a + beta[tid];
    }
    __syncthreads();
    for (int i = tid; i < OC*OC; i += 512) {
        int o = i / OC, c = i % OC;
        Wd[o*WRS + c] = tf32r(fw[i] * alpha[o]);
    }
    for (int i = tid; i < OC*FP2; i += 512) {
        int c = i / FP2, p = i % FP2;
        int gp = p0 + p;
        float v = 0.f;
        if (gp < TFT) {
            if (c < CC) v = micp[(size_t)b*CTF + (size_t)c*TFT + gp];
            else        v = g_ref[(size_t)b*CTF + (size_t)(c-CC)*TFT + gp];
        }
        combT[p*CTS + c] = tf32r(v);
    }
    __syncthreads();

    const int w = tid >> 5, lane = tid & 31;
    const int tg = lane >> 2, t4 = lane & 3;
    const float pa = prelu_a[0];
    const size_t obase = (size_t)b*OC*TFT;
    const int n0 = w * 8;

    unsigned bf[12][2];
    #pragma unroll
    for (int kk = 0; kk < 12; kk++) {
        const float* pp = &combT[(n0 + tg)*CTS + kk*8 + t4];
        bf[kk][0] = __float_as_uint(pp[0]);
        bf[kk][1] = __float_as_uint(pp[4]);
    }

    const int pg = p0 + n0 + 2*t4;
    #pragma unroll 2
    for (int mb = 0; mb < 6; mb++) {
        const int m0 = mb * 16;
        float c0=0.f, c1=0.f, c2=0.f, c3=0.f;
        #pragma unroll
        for (int kk = 0; kk < 12; kk++) {
            const float* q = &Wd[(m0 + tg)*WRS + kk*8 + t4];
            unsigned a0 = __float_as_uint(q[0]);
            unsigned a1 = __float_as_uint(q[8*WRS]);
            unsigned a2 = __float_as_uint(q[4]);
            unsigned a3 = __float_as_uint(q[8*WRS + 4]);
            mma_tf32(c0, c1, c2, c3, a0, a1, a2, a3, bf[kk][0], bf[kk][1]);
        }
        const int o0 = m0 + tg, o1 = o0 + 8;
        if (pg < TFT) {
            float bs0 = bias[o0], bs1 = bias[o1];
            float y0 = c0 + bs0, y1 = c1 + bs0;
            float y2 = c2 + bs1, y3 = c3 + bs1;
            y0 = (y0 >= 0.f) ? y0 : pa*y0;
            y1 = (y1 >= 0.f) ? y1 : pa*y1;
            y2 = (y2 >= 0.f) ? y2 : pa*y2;
            y3 = (y3 >= 0.f) ? y3 : pa*y3;
            *(float2*)&outp[obase + (size_t)o0*TFT + pg] = make_float2(y0, y1);
            *(float2*)&outp[obase + (size_t)o1*TFT + pg] = make_float2(y2, y3);
        }
    }
}

// ---------------------------------------------------------------------------
extern "C" void kernel_launch(void* const* d_in, const int* in_sizes, int n_in,
                              void* d_out, int out_size)
{
    const float* x_mic = (const float*)d_in[0];
    const float* x_ref = (const float*)d_in[1];
    const float* dw1w = (const float*)d_in[2];
    const float* dw1b = (const float*)d_in[3];
    const float* pw1w = (const float*)d_in[4];
    const float* pw1b = (const float*)d_in[5];
    const float* dw2w = (const float*)d_in[6];
    const float* dw2b = (const float*)d_in[7];
    const float* pw2w = (const float*)d_in[8];
    const float* pw2b = (const float*)d_in[9];
    const float* dw3w = (const float*)d_in[10];
    const float* dw3b = (const float*)d_in[11];
    const float* pw3w = (const float*)d_in[12];
    const float* pw3b = (const float*)d_in[13];
    const float* fw   = (const float*)d_in[14];
    const float* fb   = (const float*)d_in[15];
    const float* gam  = (const float*)d_in[16];
    const float* bet  = (const float*)d_in[17];
    const float* mea  = (const float*)d_in[18];
    const float* var  = (const float*)d_in[19];
    const float* pa   = (const float*)d_in[20];

    float* outp = (float*)d_out;
    float* micp = outp + OUT_SZ;    // second tuple output region

    cudaFuncSetAttribute(pw_kernel,
                         cudaFuncAttributeMaxDynamicSharedMemorySize, SMEM_PW);
    cudaFuncSetAttribute(mic_attn_kernel,
                         cudaFuncAttributeMaxDynamicSharedMemorySize, SMEM_MMA);
    cudaFuncSetAttribute(fusion_kernel,
                         cudaFuncAttributeMaxDynamicSharedMemorySize, SMEM_FUS);

    pw_kernel<<<dim3(PW_NB, BB, 2), 384, SMEM_PW>>>(
        x_mic, x_ref, dw1w, dw1b, pw1w, pw1b, dw2w, dw2b, pw2w, pw2b,
        dw3w, dw3b, pw3w, pw3b);
    mic_attn_kernel<<<dim3(TT, BB), 512, SMEM_MMA>>>(x_mic, micp);
    ref_attn_kernel<<<dim3(TT/8, CC, BB), 256>>>(x_ref);
    fusion_kernel<<<dim3(FNB, BB), 512, SMEM_FUS>>>(
        fw, fb, gam, bet, mea, var, pa, micp, outp);
}

// round 16
// speedup vs baseline: 1.0756x; 1.0756x over previous
#include <cuda_runtime.h>
#include <math.h>

#define CC 48
#define TT 400
#define FF 129
#define BB 2
#define TFT 51600        // T*F
#define CTF 2476800      // C*T*F
#define BCTF 4953600     // B*C*T*F
#define OC 96
#define OUT_SZ 9907200   // B*OC*T*F

// ---- tf32 helpers (validated R12-R15) ----
__device__ __forceinline__ float tf32r(float x) {
    unsigned y; asm("cvt.rna.tf32.f32 %0, %1;" : "=r"(y) : "f"(x));
    return __uint_as_float(y);
}
__device__ __forceinline__ void mma_tf32(
    float &c0, float &c1, float &c2, float &c3,
    unsigned a0, unsigned a1, unsigned a2, unsigned a3,
    unsigned b0, unsigned b1)
{
    asm("mma.sync.aligned.m16n8k8.row.col.f32.tf32.tf32.f32 "
        "{%0,%1,%2,%3}, {%4,%5,%6,%7}, {%8,%9}, {%0,%1,%2,%3};"
        : "+f"(c0), "+f"(c1), "+f"(c2), "+f"(c3)
        : "r"(a0), "r"(a1), "r"(a2), "r"(a3), "r"(b0), "r"(b1));
}

// Scratch
__device__ __align__(16) float g_Q[BCTF];
__device__ __align__(16) float g_K[BCTF];
__device__ __align__(16) float g_Kref[BCTF];
__device__ __align__(16) float g_ref[BCTF];

// ===========================================================================
// Kernel 1: pw via tf32 mma (fusion-style). z=0: Q=pw1(dw1(x_mic)) then
// K=pw2(dw2(Q)) (Q->K chained through transposed smem tile). z=1: Kref.
// A = folded W[o][c] (m=o: 3 tiles, k=c: 6 steps); B = xT[p][c] (n=p: 16
// tiles, one per warp, frags cached). 512 thr, 73.6KB -> 2 CTAs/SM.
// ===========================================================================
#define PWM_P 128
#define PW_NB 404        // ceil(51600/128)
#define PWS 52           // row stride: (52*tg+t4)%32 all-distinct -> no conflicts
#define PSM_W1 0                         // [48][PWS]
#define PSM_W2 (PSM_W1 + CC*PWS)         // [48][PWS]
#define PSM_X  (PSM_W2 + CC*PWS)         // [128][PWS]  x transposed
#define PSM_QT (PSM_X + PWM_P*PWS)       // [128][PWS]  Q transposed (stage 2 B)
#define PSM_B1 (PSM_QT + PWM_P*PWS)      // [48]
#define PSM_B2 (PSM_B1 + CC)             // [48]
#define SMEM_PWM ((PSM_B2 + CC)*4)       // 73,600 B

__global__ __launch_bounds__(512) void pw_kernel(
    const float* __restrict__ x_mic, const float* __restrict__ x_ref,
    const float* __restrict__ dw1w, const float* __restrict__ dw1b,
    const float* __restrict__ pw1w, const float* __restrict__ pw1b,
    const float* __restrict__ dw2w, const float* __restrict__ dw2b,
    const float* __restrict__ pw2w, const float* __restrict__ pw2b,
    const float* __restrict__ dw3w, const float* __restrict__ dw3b,
    const float* __restrict__ pw3w, const float* __restrict__ pw3b)
{
    extern __shared__ float smp[];
    float* W1d = smp + PSM_W1;
    float* W2d = smp + PSM_W2;
    float* xT  = smp + PSM_X;
    float* qT  = smp + PSM_QT;
    float* bb1 = smp + PSM_B1;
    float* bb2 = smp + PSM_B2;

    const int tid = threadIdx.x;
    const int b = blockIdx.y, job = blockIdx.z;
    const int p0 = blockIdx.x * PWM_P;
    const float* x   = job ? x_ref : x_mic;
    const float* w1  = job ? pw3w : pw1w;
    const float* d1w = job ? dw3w : dw1w;
    const float* p1b = job ? pw3b : pw1b;
    const float* d1b = job ? dw3b : dw1b;

    for (int i = tid; i < CC*CC; i += 512) {
        int o = i / CC, c = i % CC;
        W1d[o*PWS + c] = tf32r(w1[i] * d1w[c]);
        if (!job) W2d[o*PWS + c] = tf32r(pw2w[i] * dw2w[c]);
    }
    if (tid < CC) {
        float s1 = p1b[tid];
        for (int c = 0; c < CC; c++) s1 += w1[tid*CC+c] * d1b[c];
        bb1[tid] = s1;
        if (!job) {
            float s2 = pw2b[tid];
            for (int c = 0; c < CC; c++) s2 += pw2w[tid*CC+c] * dw2b[c];
            bb2[tid] = s2;
        }
    }
    for (int i = tid; i < CC*PWM_P; i += 512) {
        int c = i / PWM_P, p = i % PWM_P;
        int gp = p0 + p;
        xT[p*PWS + c] = (gp < TFT) ? tf32r(x[(size_t)b*CTF + (size_t)c*TFT + gp]) : 0.f;
    }
    __syncthreads();

    const int w = tid >> 5, lane = tid & 31;   // 16 warps: warp = n-tile (p)
    const int tg = lane >> 2, t4 = lane & 3;
    const int n0 = w * 8;
    const int pgb = p0 + n0 + 2*t4;            // even; TFT even -> pair-safe
    float* out1 = job ? g_Kref : g_Q;

    // ---- stage 1: Q (or Kref) ----
    {
        unsigned bf[6][2];
        #pragma unroll
        for (int kk = 0; kk < 6; kk++) {
            const float* pp = &xT[(n0 + tg)*PWS + kk*8 + t4];
            bf[kk][0] = __float_as_uint(pp[0]);
            bf[kk][1] = __float_as_uint(pp[4]);
        }
        #pragma unroll
        for (int mb = 0; mb < 3; mb++) {
            const int m0 = mb * 16;
            float c0=0.f, c1=0.f, c2=0.f, c3=0.f;
            #pragma unroll
            for (int kk = 0; kk < 6; kk++) {
                const float* q = &W1d[(m0 + tg)*PWS + kk*8 + t4];
                unsigned a0 = __float_as_uint(q[0]);
                unsigned a1 = __float_as_uint(q[8*PWS]);
                unsigned a2 = __float_as_uint(q[4]);
                unsigned a3 = __float_as_uint(q[8*PWS + 4]);
                mma_tf32(c0, c1, c2, c3, a0, a1, a2, a3, bf[kk][0], bf[kk][1]);
            }
            const int o0 = m0 + tg, o1 = o0 + 8;
            float q0 = c0 + bb1[o0], q1 = c1 + bb1[o0];
            float q2 = c2 + bb1[o1], q3 = c3 + bb1[o1];
            if (pgb < TFT) {
                size_t base = (size_t)b*CTF + pgb;
                *(float2*)&out1[base + (size_t)o0*TFT] = make_float2(q0, q1);
                *(float2*)&out1[base + (size_t)o1*TFT] = make_float2(q2, q3);
            }
            if (!job) {   // conflict-free scattered STS (8t4+tg all-distinct)
                qT[(n0 + 2*t4)*PWS + o0]     = tf32r(q0);
                qT[(n0 + 2*t4 + 1)*PWS + o0] = tf32r(q1);
                qT[(n0 + 2*t4)*PWS + o1]     = tf32r(q2);
                qT[(n0 + 2*t4 + 1)*PWS + o1] = tf32r(q3);
            }
        }
    }
    if (job) return;
    __syncthreads();

    // ---- stage 2: K = pw2(dw2(Q)) from qT ----
    {
        unsigned bf[6][2];
        #pragma unroll
        for (int kk = 0; kk < 6; kk++) {
            const float* pp = &qT[(n0 + tg)*PWS + kk*8 + t4];
            bf[kk][0] = __float_as_uint(pp[0]);
            bf[kk][1] = __float_as_uint(pp[4]);
        }
        #pragma unroll
        for (int mb = 0; mb < 3; mb++) {
            const int m0 = mb * 16;
            float c0=0.f, c1=0.f, c2=0.f, c3=0.f;
            #pragma unroll
            for (int kk = 0; kk < 6; kk++) {
                const float* q = &W2d[(m0 + tg)*PWS + kk*8 + t4];
                unsigned a0 = __float_as_uint(q[0]);
                unsigned a1 = __float_as_uint(q[8*PWS]);
                unsigned a2 = __float_as_uint(q[4]);
                unsigned a3 = __float_as_uint(q[8*PWS + 4]);
                mma_tf32(c0, c1, c2, c3, a0, a1, a2, a3, bf[kk][0], bf[kk][1]);
            }
            const int o0 = m0 + tg, o1 = o0 + 8;
            if (pgb < TFT) {
                size_t base = (size_t)b*CTF + pgb;
                *(float2*)&g_K[base + (size_t)o0*TFT] =
                    make_float2(c0 + bb2[o0], c1 + bb2[o0]);
                *(float2*)&g_K[base + (size_t)o1*TFT] =
                    make_float2(c2 + bb2[o1], c3 + bb2[o1]);
            }
        }
    }
}

// ===========================================================================
// Kernel 2: mic attention via tf32 mma (exact R12/R14 version, 256 threads —
// R15 proved 512 threads regress at 1 CTA/SM)
// ===========================================================================
#define QSTR 52
#define SSTR 137
#define XSTR 140
#define SM_Q 0
#define SM_K (SM_Q + 144*QSTR)
#define SM_X (SM_K + 136*QSTR)
#define SM_S (SM_X + 48*XSTR)
#define SM_IV (SM_S + 136*SSTR)
#define SMEM_MMA ((SM_IV + 132)*4)   // 160,176 B

__global__ __launch_bounds__(256) void mic_attn_kernel(
    const float* __restrict__ x_mic, float* __restrict__ mic_out)
{
    extern __shared__ float sm[];
    float* Qs = sm + SM_Q;
    float* Ks = sm + SM_K;
    float* Xs = sm + SM_X;
    float* Ss = sm + SM_S;
    float* SIv = sm + SM_IV;

    const int tid = threadIdx.x;
    const int t = blockIdx.x, b = blockIdx.y;
    const size_t rbase = (size_t)b*CTF + (size_t)t*FF;

    for (int i = tid; i < CC*144; i += 256) {
        int c = i / 144, f = i % 144;
        Qs[f*QSTR + c] = (f < FF) ? tf32r(g_Q[rbase + (size_t)c*TFT + f]) : 0.f;
    }
    for (int i = tid; i < CC*136; i += 256) {
        int c = i / 136, g = i % 136;
        Ks[g*QSTR + c] = (g < FF) ? tf32r(g_K[rbase + (size_t)c*TFT + g]) : 0.f;
    }
    for (int i = tid; i < CC*XSTR; i += 256) {
        int c = i / XSTR, g = i % XSTR;
        Xs[c*XSTR + g] = (g < FF) ? tf32r(x_mic[rbase + (size_t)c*TFT + g]) : 0.f;
    }
    __syncthreads();

    const int w = tid >> 5, lane = tid & 31;
    const int tg = lane >> 2, t4 = lane & 3;

    for (int mt = w; mt < 9; mt += 8) {
        const int m0 = mt * 16;
        unsigned a[6][4];
        #pragma unroll
        for (int kk = 0; kk < 6; kk++) {
            const float* q = &Qs[(m0 + tg)*QSTR + kk*8 + t4];
            a[kk][0] = __float_as_uint(q[0]);
            a[kk][1] = __float_as_uint(q[8*QSTR]);
            a[kk][2] = __float_as_uint(q[4]);
            a[kk][3] = __float_as_uint(q[8*QSTR + 4]);
        }
        for (int nt = 0; nt < 17; nt++) {
            const int n0 = nt * 8;
            float c0=0.f, c1=0.f, c2=0.f, c3=0.f;
            #pragma unroll
            for (int kk = 0; kk < 6; kk++) {
                const float* kp = &Ks[(n0 + tg)*QSTR + kk*8 + t4];
                unsigned b0 = __float_as_uint(kp[0]);
                unsigned b1 = __float_as_uint(kp[4]);
                mma_tf32(c0, c1, c2, c3,
                         a[kk][0], a[kk][1], a[kk][2], a[kk][3], b0, b1);
            }
            int r0 = m0 + tg, r1 = r0 + 8;
            int cc = n0 + 2*t4;
            if (r0 < FF) { Ss[r0*SSTR + cc] = c0; Ss[r0*SSTR + cc + 1] = c1; }
            if (r1 < FF) { Ss[r1*SSTR + cc] = c2; Ss[r1*SSTR + cc + 1] = c3; }
        }
    }
    __syncthreads();

    if (tid < FF) {
        float* row = &Ss[tid*SSTR];
        const float rs = 0.14433756729740643f;
        float s0=0.f, s1=0.f, s2=0.f, s3=0.f;
        #pragma unroll 1
        for (int g = 0; g < 128; g += 4) {
            float e0 = tf32r(__expf(row[g+0]*rs));
            float e1 = tf32r(__expf(row[g+1]*rs));
            float e2 = tf32r(__expf(row[g+2]*rs));
            float e3 = tf32r(__expf(row[g+3]*rs));
            row[g+0]=e0; row[g+1]=e1; row[g+2]=e2; row[g+3]=e3;
            s0+=e0; s1+=e1; s2+=e2; s3+=e3;
        }
        float e = tf32r(__expf(row[128]*rs));
        row[128] = e;
        SIv[tid] = 1.f / (s0+s1+s2+s3+e);
    }
    __syncthreads();

    for (int job = w; job < 51; job += 8) {
        const int m0 = (job / 17) * 16;
        const int n0 = (job % 17) * 8;
        float c0=0.f, c1=0.f, c2=0.f, c3=0.f;
        #pragma unroll 4
        for (int kk = 0; kk < 17; kk++) {
            const float* xp = &Xs[(m0 + tg)*XSTR + kk*8 + t4];
            unsigned a0 = __float_as_uint(xp[0]);
            unsigned a1 = __float_as_uint(xp[8*XSTR]);
            unsigned a2 = __float_as_uint(xp[4]);
            unsigned a3 = __float_as_uint(xp[8*XSTR + 4]);
            const float* pp = &Ss[(n0 + tg)*SSTR + kk*8 + t4];
            unsigned b0 = __float_as_uint(pp[0]);
            unsigned b1 = __float_as_uint(pp[4]);
            mma_tf32(c0, c1, c2, c3, a0, a1, a2, a3, b0, b1);
        }
        const int r0 = m0 + tg, r1 = r0 + 8;
        const int f0 = n0 + 2*t4;
        if (f0 < FF) {
            float iv = SIv[f0];
            mic_out[rbase + (size_t)r0*TFT + f0] = c0 * iv;
            mic_out[rbase + (size_t)r1*TFT + f0] = c2 * iv;
        }
        if (f0 + 1 < FF) {
            float iv = SIv[f0 + 1];
            mic_out[rbase + (size_t)r0*TFT + f0 + 1] = c1 * iv;
            mic_out[rbase + (size_t)r1*TFT + f0 + 1] = c3 * iv;
        }
    }
}

// ===========================================================================
// Kernel 3: ref attention (exact R10 version)
// ===========================================================================
#define RFP 132

__global__ __launch_bounds__(256) void ref_attn_kernel(const float* __restrict__ x_ref)
{
    __shared__ __align__(16) float krs[18*RFP];
    __shared__ __align__(16) float xrs[18*RFP];

    const int tid = threadIdx.x;
    const int t0 = blockIdx.x * 8;
    const int h = blockIdx.y, b = blockIdx.z;
    const size_t base = (size_t)b*CTF + (size_t)h*TFT;

    for (int i = tid; i < 18*RFP; i += 256) {
        int r = i / RFP, f = i % RFP;
        int tk = t0 - 10 + r;
        bool ok = (tk >= 0) && (f < FF);
        size_t gi = base + (size_t)tk*FF + f;
        krs[i] = ok ? g_Kref[gi] : 0.f;
        xrs[i] = ok ? x_ref[gi]  : 0.f;
    }
    __syncthreads();

    const int w = tid >> 5, lane = tid & 31;
    const int t = t0 + w;
    const size_t qbase = base + (size_t)t*FF;

    float qv[5], acc[5];
    bool val[5];
    #pragma unroll
    for (int k = 0; k < 5; k++) {
        int f = lane + 32*k;
        val[k] = f < FF;
        qv[k] = val[k] ? g_Q[qbase + f] : 0.f;
        acc[k] = 0.f;
    }

    for (int j = 0; j < 11; j++) {
        int tk = t - 10 + j;
        if (tk < 0) continue;
        int r = w + j;
        float e[5]; float s = 0.f;
        float xv[5];
        #pragma unroll
        for (int k = 0; k < 5; k++) {
            int f = lane + 32*k;
            float kv = val[k] ? krs[r*RFP+f] : 0.f;
            xv[k]    = val[k] ? xrs[r*RFP+f] : 0.f;
            e[k] = val[k] ? __expf(qv[k]*kv) : 0.f;
            s += e[k];
        }
        #pragma unroll
        for (int off = 16; off; off >>= 1) s += __shfl_xor_sync(0xffffffffu, s, off);
        float inv = 1.f/s;
        #pragma unroll
        for (int k = 0; k < 5; k++)
            acc[k] += xv[k] * (e[k]*inv);
    }
    #pragma unroll
    for (int k = 0; k < 5; k++) {
        int f = lane + 32*k;
        if (val[k]) g_ref[qbase + f] = acc[k];
    }
}

// ===========================================================================
// Kernel 4: fusion (exact R14 version, measured 67.4 µs)
// ===========================================================================
#define FP2 128
#define FNB 404
#define WRS 100
#define CTS 100
#define FSM_W 0
#define FSM_C (FSM_W + OC*WRS)
#define FSM_B (FSM_C + FP2*CTS)
#define FSM_A (FSM_B + OC)
#define SMEM_FUS ((FSM_A + OC)*4)    // 90,368 B

__global__ __launch_bounds__(512) void fusion_kernel(
    const float* __restrict__ fw, const float* __restrict__ fb,
    const float* __restrict__ gamma, const float* __restrict__ beta,
    const float* __restrict__ mean, const float* __restrict__ var,
    const float* __restrict__ prelu_a,
    const float* __restrict__ micp,
    float* __restrict__ outp)
{
    extern __shared__ float smf[];
    float* Wd    = smf + FSM_W;
    float* combT = smf + FSM_C;
    float* bias  = smf + FSM_B;
    float* alpha = smf + FSM_A;

    const int tid = threadIdx.x;
    const int b  = blockIdx.y;
    const int p0 = blockIdx.x * FP2;

    if (tid < OC) {
        float a = gamma[tid] * rsqrtf(var[tid] + 1e-5f);
        alpha[tid] = a;
        bias[tid] = (fb[tid] - mean[tid]) * a + beta[tid];
    }
    __syncthreads();
    for (int i = tid; i < OC*OC; i += 512) {
        int o = i / OC, c = i % OC;
        Wd[o*WRS + c] = tf32r(fw[i] * alpha[o]);
    }
    for (int i = tid; i < OC*FP2; i += 512) {
        int c = i / FP2, p = i % FP2;
        int gp = p0 + p;
        float v = 0.f;
        if (gp < TFT) {
            if (c < CC) v = micp[(size_t)b*CTF + (size_t)c*TFT + gp];
            else        v = g_ref[(size_t)b*CTF + (size_t)(c-CC)*TFT + gp];
        }
        combT[p*CTS + c] = tf32r(v);
    }
    __syncthreads();

    const int w = tid >> 5, lane = tid & 31;
    const int tg = lane >> 2, t4 = lane & 3;
    const float pa = prelu_a[0];
    const size_t obase = (size_t)b*OC*TFT;
    const int n0 = w * 8;

    unsigned bf[12][2];
    #pragma unroll
    for (int kk = 0; kk < 12; kk++) {
        const float* pp = &combT[(n0 + tg)*CTS + kk*8 + t4];
        bf[kk][0] = __float_as_uint(pp[0]);
        bf[kk][1] = __float_as_uint(pp[4]);
    }

    const int pg = p0 + n0 + 2*t4;
    #pragma unroll 2
    for (int mb = 0; mb < 6; mb++) {
        const int m0 = mb * 16;
        float c0=0.f, c1=0.f, c2=0.f, c3=0.f;
        #pragma unroll
        for (int kk = 0; kk < 12; kk++) {
            const float* q = &Wd[(m0 + tg)*WRS + kk*8 + t4];
            unsigned a0 = __float_as_uint(q[0]);
            unsigned a1 = __float_as_uint(q[8*WRS]);
            unsigned a2 = __float_as_uint(q[4]);
            unsigned a3 = __float_as_uint(q[8*WRS + 4]);
            mma_tf32(c0, c1, c2, c3, a0, a1, a2, a3, bf[kk][0], bf[kk][1]);
        }
        const int o0 = m0 + tg, o1 = o0 + 8;
        if (pg < TFT) {
            float bs0 = bias[o0], bs1 = bias[o1];
            float y0 = c0 + bs0, y1 = c1 + bs0;
            float y2 = c2 + bs1, y3 = c3 + bs1;
            y0 = (y0 >= 0.f) ? y0 : pa*y0;
            y1 = (y1 >= 0.f) ? y1 : pa*y1;
            y2 = (y2 >= 0.f) ? y2 : pa*y2;
            y3 = (y3 >= 0.f) ? y3 : pa*y3;
            *(float2*)&outp[obase + (size_t)o0*TFT + pg] = make_float2(y0, y1);
            *(float2*)&outp[obase + (size_t)o1*TFT + pg] = make_float2(y2, y3);
        }
    }
}

// ---------------------------------------------------------------------------
extern "C" void kernel_launch(void* const* d_in, const int* in_sizes, int n_in,
                              void* d_out, int out_size)
{
    const float* x_mic = (const float*)d_in[0];
    const float* x_ref = (const float*)d_in[1];
    const float* dw1w = (const float*)d_in[2];
    const float* dw1b = (const float*)d_in[3];
    const float* pw1w = (const float*)d_in[4];
    const float* pw1b = (const float*)d_in[5];
    const float* dw2w = (const float*)d_in[6];
    const float* dw2b = (const float*)d_in[7];
    const float* pw2w = (const float*)d_in[8];
    const float* pw2b = (const float*)d_in[9];
    const float* dw3w = (const float*)d_in[10];
    const float* dw3b = (const float*)d_in[11];
    const float* pw3w = (const float*)d_in[12];
    const float* pw3b = (const float*)d_in[13];
    const float* fw   = (const float*)d_in[14];
    const float* fb   = (const float*)d_in[15];
    const float* gam  = (const float*)d_in[16];
    const float* bet  = (const float*)d_in[17];
    const float* mea  = (const float*)d_in[18];
    const float* var  = (const float*)d_in[19];
    const float* pa   = (const float*)d_in[20];

    float* outp = (float*)d_out;
    float* micp = outp + OUT_SZ;    // second tuple output region

    cudaFuncSetAttribute(pw_kernel,
                         cudaFuncAttributeMaxDynamicSharedMemorySize, SMEM_PWM);
    cudaFuncSetAttribute(mic_attn_kernel,
                         cudaFuncAttributeMaxDynamicSharedMemorySize, SMEM_MMA);
    cudaFuncSetAttribute(fusion_kernel,
                         cudaFuncAttributeMaxDynamicSharedMemorySize, SMEM_FUS);

    pw_kernel<<<dim3(PW_NB, BB, 2), 512, SMEM_PWM>>>(
        x_mic, x_ref, dw1w, dw1b, pw1w, pw1b, dw2w, dw2b, pw2w, pw2b,
        dw3w, dw3b, pw3w, pw3b);
    mic_attn_kernel<<<dim3(TT, BB), 256, SMEM_MMA>>>(x_mic, micp);
    ref_attn_kernel<<<dim3(TT/8, CC, BB), 256>>>(x_ref);
    fusion_kernel<<<dim3(FNB, BB), 512, SMEM_FUS>>>(
        fw, fb, gam, bet, mea, var, pa, micp, outp);
}